// round 6
// baseline (speedup 1.0000x reference)
#include <cuda_runtime.h>
#include <cuda_bf16.h>
#include <cstdint>

#define NSUM 2048
#define NMAX 64
#define MFEAT 16
#define HID 128
#define OUTF 64
#define NEDGE 16384
#define NLAYER 4
#define NROWS_TOTAL (NSUM * NMAX)
#define GRID_MAIN 296

// bf16 weight buffer layout (n-major, stride = 2K+8, [hi K | lo K | pad])
#define SZ_W1F (128 * 40)
#define SZ_WR  (128 * 264)
#define SZ_W2L (64 * 264)
#define OFF_W1F 0
#define OFF_W1R (SZ_W1F)
#define OFF_W2M (OFF_W1R + 3 * SZ_WR)
#define OFF_W2L (OFF_W2M + 3 * SZ_WR)
#define WBF_TOTAL (OFF_W2L + SZ_W2L)

// ---------------------------------------------------------------------------
// Device scratch (static __device__ globals: allocation-free per harness rules)
// ---------------------------------------------------------------------------
__device__ float g_X[(size_t)NSUM * NMAX * HID];
__device__ float g_H[(size_t)NSUM * NMAX * HID];
__device__ __nv_bfloat16 g_Wbf[WBF_TOTAL];
__device__ float g_stats[NLAYER * 2 * HID];
__device__ float g_bnp[NLAYER * 2 * HID];
__device__ int   g_off[NSUM + 1];
__device__ int   g_csr[NEDGE];

// ---------------------------------------------------------------------------
// Merged CSR build: count -> scan -> fill, single CTA (1024 threads).
// Also zeroes the BN stats accumulators for this call.
// ---------------------------------------------------------------------------
__global__ void gin_csr(const int* __restrict__ src, const int* __restrict__ dst)
{
    __shared__ int s0[NSUM], s1[NSUM], cur[NSUM];
    const int t = threadIdx.x;            // 1024 threads

    g_stats[t] = 0.f;                     // 4*2*128 == 1024 exactly
    #pragma unroll
    for (int j = 0; j < 2; j++) { s0[t + j * 1024] = 0; cur[t + j * 1024] = 0; }
    __syncthreads();

    // count (smem atomics)
    #pragma unroll
    for (int j = 0; j < NEDGE / 1024; j++)
        atomicAdd(&s0[dst[t + j * 1024]], 1);
    __syncthreads();

    // inclusive scan over 2048
    int* in = s0; int* out = s1;
    for (int d = 1; d < NSUM; d <<= 1) {
        #pragma unroll
        for (int j = 0; j < 2; j++) {
            int i = t + j * 1024;
            int v = in[i];
            if (i >= d) v += in[i - d];
            out[i] = v;
        }
        __syncthreads();
        int* tmp = in; in = out; out = tmp;
    }
    if (t == 0) g_off[0] = 0;
    #pragma unroll
    for (int j = 0; j < 2; j++) g_off[t + j * 1024 + 1] = in[t + j * 1024];
    __syncthreads();

    // fill
    #pragma unroll
    for (int j = 0; j < NEDGE / 1024; j++) {
        int e = t + j * 1024;
        int d = dst[e];
        int p = atomicAdd(&cur[d], 1);
        g_csr[in[d] - (in[d] - (d ? in[d - 1] : 0)) + p] = src[e];   // off[d] = in[d-1]
    }
}

// ---------------------------------------------------------------------------
// Weight conversion: fp32 [K][N] -> bf16 hi/lo, n-major [N][2K+pad]
// ---------------------------------------------------------------------------
__global__ void gin_wconv(const float* __restrict__ W1f, const float* __restrict__ W1r,
                          const float* __restrict__ W2m, const float* __restrict__ W2l)
{
    int idx = blockIdx.x * 256 + threadIdx.x;
    float w; int k, n, K; size_t doff; int sa;
    if (idx < 2048) {
        K = 16; k = idx / 128; n = idx % 128;
        w = W1f[idx]; doff = OFF_W1F; sa = 40;
    } else if (idx < 2048 + 3 * 16384) {
        int e = idx - 2048; int l = e / 16384; int r = e % 16384;
        K = 128; k = r / 128; n = r % 128;
        w = W1r[e]; doff = OFF_W1R + (size_t)l * SZ_WR; sa = 264;
    } else if (idx < 2048 + 6 * 16384) {
        int e = idx - 2048 - 3 * 16384; int l = e / 16384; int r = e % 16384;
        K = 128; k = r / 128; n = r % 128;
        w = W2m[e]; doff = OFF_W2M + (size_t)l * SZ_WR; sa = 264;
    } else if (idx < 2048 + 6 * 16384 + 8192) {
        int e = idx - 2048 - 6 * 16384;
        K = 128; k = e / 64; n = e % 64;
        w = W2l[e]; doff = OFF_W2L; sa = 264;
    } else return;
    __nv_bfloat16 hi = __float2bfloat16(w);
    __nv_bfloat16 lo = __float2bfloat16(w - __bfloat162float(hi));
    g_Wbf[doff + (size_t)n * sa + k]     = hi;
    g_Wbf[doff + (size_t)n * sa + K + k] = lo;
}

// ---------------------------------------------------------------------------
// MMA helpers
// ---------------------------------------------------------------------------
__device__ __forceinline__ void ldsm4(uint32_t* r, uint32_t a)
{
    asm volatile("ldmatrix.sync.aligned.m8n8.x4.shared.b16 {%0,%1,%2,%3}, [%4];"
                 : "=r"(r[0]), "=r"(r[1]), "=r"(r[2]), "=r"(r[3]) : "r"(a));
}

__device__ __forceinline__ void mma_bf16(float* d, const uint32_t* a, uint32_t b0, uint32_t b1)
{
    asm volatile("mma.sync.aligned.m16n8k16.row.col.f32.bf16.bf16.f32 "
                 "{%0,%1,%2,%3},{%4,%5,%6,%7},{%8,%9},{%0,%1,%2,%3};"
                 : "+f"(d[0]), "+f"(d[1]), "+f"(d[2]), "+f"(d[3])
                 : "r"(a[0]), "r"(a[1]), "r"(a[2]), "r"(a[3]), "r"(b0), "r"(b1));
}

// hi/lo bf16 convert + store of a float4 row-chunk
__device__ __forceinline__ void cvt_store(__nv_bfloat16* dhi, __nv_bfloat16* dlo, float4 v)
{
    __nv_bfloat16 h0 = __float2bfloat16(v.x), h1 = __float2bfloat16(v.y);
    __nv_bfloat16 h2 = __float2bfloat16(v.z), h3 = __float2bfloat16(v.w);
    __nv_bfloat162 a; a.x = h0; a.y = h1;
    __nv_bfloat162 b; b.x = h2; b.y = h3;
    ((__nv_bfloat162*)dhi)[0] = a; ((__nv_bfloat162*)dhi)[1] = b;
    __nv_bfloat162 c, d;
    c.x = __float2bfloat16(v.x - __bfloat162float(h0));
    c.y = __float2bfloat16(v.y - __bfloat162float(h1));
    d.x = __float2bfloat16(v.z - __bfloat162float(h2));
    d.y = __float2bfloat16(v.w - __bfloat162float(h3));
    ((__nv_bfloat162*)dlo)[0] = c; ((__nv_bfloat162*)dlo)[1] = d;
}

// GEMM core: 3 segments (hi*hi + lo*hi + hi*lo), KH/16 ksteps each.
template <int KH, int MT>
__device__ __forceinline__ void gemm_mma(const uint32_t* aBase, const uint32_t* bBase,
                                         int kaSel, int kbSel, float (*acc)[4][4])
{
    #pragma unroll
    for (int seg = 0; seg < 3; seg++) {
        const int aoff = (seg == 1) ? KH : 0;
        const int boff = (seg == 2) ? KH : 0;
        #pragma unroll
        for (int ks = 0; ks < KH / 16; ks++) {
            const int ka = (aoff + ks * 16 + kaSel) * 2;
            const int kb = (boff + ks * 16 + kbSel) * 2;
            uint32_t a[MT][4], b[2][4];
            #pragma unroll
            for (int mi = 0; mi < MT; mi++) ldsm4(a[mi], aBase[mi] + ka);
            #pragma unroll
            for (int p = 0; p < 2; p++) ldsm4(b[p], bBase[p] + kb);
            #pragma unroll
            for (int mi = 0; mi < MT; mi++)
                #pragma unroll
                for (int ni = 0; ni < 4; ni++)
                    mma_bf16(acc[mi][ni], a[mi], b[ni >> 1][(ni & 1) * 2], b[ni >> 1][(ni & 1) * 2 + 1]);
        }
    }
}

// ---------------------------------------------------------------------------
// Kernel A: gather + (1+eps)X + GEMM1 (bf16x3 MMA) + BN stat partials
// ---------------------------------------------------------------------------
template <int KH>
__global__ void __launch_bounds__(256, 2)
gin_A(const float* __restrict__ Xin, const __nv_bfloat16* __restrict__ Wg,
      const float* __restrict__ b1, const float* __restrict__ epsArr, int layer,
      float* __restrict__ Hout, float* __restrict__ gsum, float* __restrict__ gsq)
{
    constexpr int SA  = 2 * KH + 8;
    constexpr int KC4 = KH / 4;
    constexpr int EPT = 64 * KC4 / 256;
    extern __shared__ float smf[];
    __nv_bfloat16* Ws = (__nv_bfloat16*)smf;     // 128*SA
    __nv_bfloat16* As = Ws + 128 * SA;           // 64*SA
    float* sb = (float*)(As + 64 * SA);          // 128

    const int tid  = threadIdx.x;
    const int lane = tid & 31, wid = tid >> 5;
    const int wm = wid & 1, wn = wid >> 1;       // 2 (m) x 4 (n) warps
    const int grp = lane >> 2, tig = lane & 3;
    const int sel = lane >> 3, l7 = lane & 7;
    const float epl = 1.f + epsArr[layer];

    {   // stage weights + bias
        const uint4* s = (const uint4*)Wg;
        uint4* d = (uint4*)Ws;
        for (int i = tid; i < 128 * SA / 8; i += 256) d[i] = s[i];
        if (tid < 128) sb[tid] = b1[tid];
    }

    uint32_t aBase[2], bBase[2];
    {
        uint32_t asb = (uint32_t)__cvta_generic_to_shared(As);
        uint32_t wsb = (uint32_t)__cvta_generic_to_shared(Ws);
        aBase[0] = asb + (uint32_t)((wm * 32 + l7 + (sel & 1) * 8) * SA) * 2;
        aBase[1] = aBase[0] + 16 * SA * 2;
        bBase[0] = wsb + (uint32_t)((wn * 32 + l7 + (sel >> 1) * 8) * SA) * 2;
        bBase[1] = bBase[0] + 16 * SA * 2;
    }
    const int kaSel = (sel >> 1) * 8, kbSel = (sel & 1) * 8;

    float psum[8], psq[8];
    #pragma unroll
    for (int q = 0; q < 8; q++) { psum[q] = 0.f; psq[q] = 0.f; }

    __syncthreads();

    for (int n = blockIdx.x; n < NSUM; n += GRID_MAIN) {
        // ---- gather: Z = (1+eps)X[n] + sum X[src], edge loop 2x-unrolled ----
        float4 r[EPT];
        const float4* xn = (const float4*)(Xin + (size_t)n * 64 * KH);
        #pragma unroll
        for (int j = 0; j < EPT; j++) {
            float4 v = xn[tid + j * 256];
            r[j].x = v.x * epl; r[j].y = v.y * epl; r[j].z = v.z * epl; r[j].w = v.w * epl;
        }
        const int eB = g_off[n], eE = g_off[n + 1];
        int e = eB;
        for (; e + 2 <= eE; e += 2) {
            const float4* xs0 = (const float4*)(Xin + (size_t)g_csr[e] * 64 * KH);
            const float4* xs1 = (const float4*)(Xin + (size_t)g_csr[e + 1] * 64 * KH);
            #pragma unroll
            for (int j = 0; j < EPT; j++) {
                float4 v0 = xs0[tid + j * 256];
                float4 v1 = xs1[tid + j * 256];
                r[j].x += v0.x + v1.x; r[j].y += v0.y + v1.y;
                r[j].z += v0.z + v1.z; r[j].w += v0.w + v1.w;
            }
        }
        if (e < eE) {
            const float4* xs = (const float4*)(Xin + (size_t)g_csr[e] * 64 * KH);
            #pragma unroll
            for (int j = 0; j < EPT; j++) {
                float4 v = xs[tid + j * 256];
                r[j].x += v.x; r[j].y += v.y; r[j].z += v.z; r[j].w += v.w;
            }
        }
        #pragma unroll
        for (int j = 0; j < EPT; j++) {
            int i = tid + j * 256;
            int row = i / KC4, col = (i % KC4) * 4;
            cvt_store(&As[row * SA + col], &As[row * SA + KH + col], r[j]);
        }
        __syncthreads();

        // ---- GEMM ----
        float acc[2][4][4];
        #pragma unroll
        for (int mi = 0; mi < 2; mi++)
            #pragma unroll
            for (int ni = 0; ni < 4; ni++) {
                int c0 = wn * 32 + ni * 8 + tig * 2;
                acc[mi][ni][0] = sb[c0];     acc[mi][ni][1] = sb[c0 + 1];
                acc[mi][ni][2] = sb[c0];     acc[mi][ni][3] = sb[c0 + 1];
            }
        gemm_mma<KH, 2>(aBase, bBase, kaSel, kbSel, acc);

        // ---- epilogue: H + BN partials ----
        float* hb = Hout + (size_t)n * 64 * 128;
        #pragma unroll
        for (int mi = 0; mi < 2; mi++) {
            int r0 = wm * 32 + mi * 16 + grp;
            #pragma unroll
            for (int ni = 0; ni < 4; ni++) {
                int c0 = wn * 32 + ni * 8 + tig * 2;
                float2 v0 = make_float2(acc[mi][ni][0], acc[mi][ni][1]);
                float2 v1 = make_float2(acc[mi][ni][2], acc[mi][ni][3]);
                *(float2*)&hb[(size_t)r0 * 128 + c0]       = v0;
                *(float2*)&hb[(size_t)(r0 + 8) * 128 + c0] = v1;
                psum[ni * 2 + 0] += v0.x + v1.x;
                psum[ni * 2 + 1] += v0.y + v1.y;
                psq[ni * 2 + 0]  += v0.x * v0.x + v1.x * v1.x;
                psq[ni * 2 + 1]  += v0.y * v0.y + v1.y * v1.y;
            }
        }
        __syncthreads();
    }

    // ---- CTA-end BN reduction (shuffle, then global atomics) ----
    #pragma unroll
    for (int q = 0; q < 8; q++) {
        float s = psum[q], ss = psq[q];
        s  += __shfl_xor_sync(0xffffffffu, s, 4);
        s  += __shfl_xor_sync(0xffffffffu, s, 8);
        s  += __shfl_xor_sync(0xffffffffu, s, 16);
        ss += __shfl_xor_sync(0xffffffffu, ss, 4);
        ss += __shfl_xor_sync(0xffffffffu, ss, 8);
        ss += __shfl_xor_sync(0xffffffffu, ss, 16);
        if (lane < 4) {
            int c = wn * 32 + (q >> 1) * 8 + lane * 2 + (q & 1);
            atomicAdd(&gsum[c], s);
            atomicAdd(&gsq[c], ss);
        }
    }
}

// ---------------------------------------------------------------------------
// Kernel B: finalize BN into scale/shift
// ---------------------------------------------------------------------------
__global__ void gin_bn(const float* __restrict__ gsum, const float* __restrict__ gsq,
                       const float* __restrict__ gamma, const float* __restrict__ beta,
                       float* __restrict__ bnp)
{
    int c = threadIdx.x;                  // 128 threads
    const float inv = 1.f / (float)NROWS_TOTAL;
    float mu  = gsum[c] * inv;
    float var = gsq[c] * inv - mu * mu;
    float rs  = rsqrtf(var + 1e-5f);
    float scl = rs * gamma[c];
    bnp[c] = scl;
    bnp[128 + c] = beta[c] - mu * scl;
}

// ---------------------------------------------------------------------------
// Kernel C: BN + ReLU + GEMM2 (bf16x3 MMA); LAST fuses masked PE reduction
// ---------------------------------------------------------------------------
template <int NOUT, bool LAST>
__global__ void __launch_bounds__(256, 2)
gin_C(const float* __restrict__ Hin, const __nv_bfloat16* __restrict__ Wg,
      const float* __restrict__ b2, const float* __restrict__ bnp,
      float* __restrict__ Xout, const float* __restrict__ mask, float* __restrict__ pe)
{
    constexpr int KH = 128, SA = 264;
    constexpr int WGM = (NOUT == 128) ? 2 : 4;
    constexpr int MT  = (NOUT == 128) ? 2 : 1;
    extern __shared__ float smf[];
    __nv_bfloat16* Ws = (__nv_bfloat16*)smf;     // NOUT*SA
    __nv_bfloat16* As = Ws + NOUT * SA;          // 64*SA
    float* sb  = (float*)(As + 64 * SA);         // NOUT
    float* ssc = sb + NOUT;                      // 128
    float* ssh = ssc + 128;                      // 128
    float* spe = ssh + 128;                      // 64 (LAST only)

    const int tid  = threadIdx.x;
    const int lane = tid & 31, wid = tid >> 5;
    const int wm = wid % WGM, wn = wid / WGM;
    const int grp = lane >> 2, tig = lane & 3;
    const int sel = lane >> 3, l7 = lane & 7;
    const int rowbase = wm * MT * 16, colbase = wn * 32;

    {
        const uint4* s = (const uint4*)Wg;
        uint4* d = (uint4*)Ws;
        for (int i = tid; i < NOUT * SA / 8; i += 256) d[i] = s[i];
        if (tid < NOUT) sb[tid] = b2[tid];
        if (tid < 128) { ssc[tid] = bnp[tid]; ssh[tid] = bnp[128 + tid]; }
    }

    uint32_t aBase[MT], bBase[2];
    {
        uint32_t asb = (uint32_t)__cvta_generic_to_shared(As);
        uint32_t wsb = (uint32_t)__cvta_generic_to_shared(Ws);
        #pragma unroll
        for (int mi = 0; mi < MT; mi++)
            aBase[mi] = asb + (uint32_t)((rowbase + mi * 16 + l7 + (sel & 1) * 8) * SA) * 2;
        bBase[0] = wsb + (uint32_t)((colbase + l7 + (sel >> 1) * 8) * SA) * 2;
        bBase[1] = bBase[0] + 16 * SA * 2;
    }
    const int kaSel = (sel >> 1) * 8, kbSel = (sel & 1) * 8;

    __syncthreads();

    for (int n = blockIdx.x; n < NSUM; n += GRID_MAIN) {
        // ---- BN + ReLU + hi/lo convert into A ----
        const float4* h4 = (const float4*)(Hin + (size_t)n * 64 * 128);
        #pragma unroll
        for (int j = 0; j < 8; j++) {
            int i = tid + j * 256;
            int row = i >> 5, col = (i & 31) * 4;
            float4 h = h4[i];
            float4 sc = *(const float4*)&ssc[col];
            float4 sh = *(const float4*)&ssh[col];
            float4 a;
            a.x = fmaxf(fmaf(h.x, sc.x, sh.x), 0.f);
            a.y = fmaxf(fmaf(h.y, sc.y, sh.y), 0.f);
            a.z = fmaxf(fmaf(h.z, sc.z, sh.z), 0.f);
            a.w = fmaxf(fmaf(h.w, sc.w, sh.w), 0.f);
            cvt_store(&As[row * SA + col], &As[row * SA + KH + col], a);
        }
        __syncthreads();

        // ---- GEMM ----
        float acc[MT][4][4];
        #pragma unroll
        for (int mi = 0; mi < MT; mi++)
            #pragma unroll
            for (int ni = 0; ni < 4; ni++) {
                int c0 = colbase + ni * 8 + tig * 2;
                acc[mi][ni][0] = sb[c0];     acc[mi][ni][1] = sb[c0 + 1];
                acc[mi][ni][2] = sb[c0];     acc[mi][ni][3] = sb[c0 + 1];
            }
        gemm_mma<KH, MT>(aBase, bBase, kaSel, kbSel, acc);

        if (!LAST) {
            float* xb = Xout + (size_t)n * 64 * 128;
            #pragma unroll
            for (int mi = 0; mi < MT; mi++) {
                int r0 = rowbase + mi * 16 + grp;
                #pragma unroll
                for (int ni = 0; ni < 4; ni++) {
                    int c0 = colbase + ni * 8 + tig * 2;
                    *(float2*)&xb[(size_t)r0 * 128 + c0]       = make_float2(acc[mi][ni][0], acc[mi][ni][1]);
                    *(float2*)&xb[(size_t)(r0 + 8) * 128 + c0] = make_float2(acc[mi][ni][2], acc[mi][ni][3]);
                }
            }
        } else {
            if (tid < 64) spe[tid] = 0.f;
            __syncthreads();
            float m0 = mask[(size_t)n * 64 + rowbase + grp];
            float m1 = mask[(size_t)n * 64 + rowbase + grp + 8];
            #pragma unroll
            for (int ni = 0; ni < 4; ni++) {
                float p0 = m0 * acc[0][ni][0] + m1 * acc[0][ni][2];
                float p1 = m0 * acc[0][ni][1] + m1 * acc[0][ni][3];
                p0 += __shfl_xor_sync(0xffffffffu, p0, 4);
                p0 += __shfl_xor_sync(0xffffffffu, p0, 8);
                p0 += __shfl_xor_sync(0xffffffffu, p0, 16);
                p1 += __shfl_xor_sync(0xffffffffu, p1, 4);
                p1 += __shfl_xor_sync(0xffffffffu, p1, 8);
                p1 += __shfl_xor_sync(0xffffffffu, p1, 16);
                if (lane < 4) {
                    int c = colbase + ni * 8 + lane * 2;
                    atomicAdd(&spe[c], p0);
                    atomicAdd(&spe[c + 1], p1);
                }
            }
            __syncthreads();
            if (tid < 64) pe[(size_t)n * 64 + tid] = spe[tid];
        }
        __syncthreads();
    }
}

// ---------------------------------------------------------------------------
// Host-side launch
// ---------------------------------------------------------------------------
extern "C" void kernel_launch(void* const* d_in, const int* in_sizes, int n_in,
                              void* d_out, int out_size)
{
    const float* W        = (const float*)d_in[0];
    const float* mask     = (const float*)d_in[1];
    const int*   src      = (const int*)d_in[2];
    const int*   dst      = (const int*)d_in[3];
    const float* eps      = (const float*)d_in[4];
    const float* W1_first = (const float*)d_in[5];
    const float* b1_first = (const float*)d_in[6];
    const float* W1_rest  = (const float*)d_in[7];
    const float* b1_rest  = (const float*)d_in[8];
    const float* bn_gamma = (const float*)d_in[9];
    const float* bn_beta  = (const float*)d_in[10];
    const float* W2_mid   = (const float*)d_in[11];
    const float* b2_mid   = (const float*)d_in[12];
    const float* W2_last  = (const float*)d_in[13];
    const float* b2_last  = (const float*)d_in[14];
    float* pe = (float*)d_out;

    void *pX, *pH, *pW, *pStats, *pBnp;
    cudaGetSymbolAddress(&pX, g_X);
    cudaGetSymbolAddress(&pH, g_H);
    cudaGetSymbolAddress(&pW, g_Wbf);
    cudaGetSymbolAddress(&pStats, g_stats);
    cudaGetSymbolAddress(&pBnp, g_bnp);
    float* X  = (float*)pX;
    float* H  = (float*)pH;
    __nv_bfloat16* Wbf = (__nv_bfloat16*)pW;
    float* st = (float*)pStats;
    float* bp = (float*)pBnp;

    const int smA128 = (192 * 264) * 2 + 512;                  // 101888
    const int smA16  = (192 * 40) * 2 + 512;                   // 15872
    const int smC128 = (192 * 264) * 2 + 512 + 1024;           // 102912
    const int smC64  = (128 * 264) * 2 + 256 + 1024 + 256;     // 69120

    cudaFuncSetAttribute(gin_A<128>,        cudaFuncAttributeMaxDynamicSharedMemorySize, smA128);
    cudaFuncSetAttribute(gin_A<16>,         cudaFuncAttributeMaxDynamicSharedMemorySize, smA16);
    cudaFuncSetAttribute(gin_C<128, false>, cudaFuncAttributeMaxDynamicSharedMemorySize, smC128);
    cudaFuncSetAttribute(gin_C<64, true>,   cudaFuncAttributeMaxDynamicSharedMemorySize, smC64);

    // Launch order matters for ncu (-s 5 -c 1 captures launch #6 = gin_A<128>)
    gin_csr<<<1, 1024>>>(src, dst);                            // 1
    gin_wconv<<<424, 256>>>(W1_first, W1_rest, W2_mid, W2_last); // 2

    for (int l = 0; l < NLAYER; l++) {
        float* gsum = st + l * 2 * HID;
        float* gsq  = gsum + HID;
        float* bnp  = bp + l * 2 * HID;

        if (l == 0) {
            gin_A<16><<<GRID_MAIN, 256, smA16>>>(              // 3
                W, Wbf + OFF_W1F, b1_first, eps, 0, H, gsum, gsq);
        } else {
            gin_A<128><<<GRID_MAIN, 256, smA128>>>(            // 6, 9, 12
                X, Wbf + OFF_W1R + (size_t)(l - 1) * SZ_WR,
                b1_rest + (size_t)(l - 1) * HID, eps, l, H, gsum, gsq);
        }

        gin_bn<<<1, 128>>>(gsum, gsq, bn_gamma + (size_t)l * HID, bn_beta + (size_t)l * HID, bnp);

        if (l < NLAYER - 1) {
            gin_C<128, false><<<GRID_MAIN, 256, smC128>>>(
                H, Wbf + OFF_W2M + (size_t)l * SZ_WR, b2_mid + (size_t)l * HID,
                bnp, X, nullptr, nullptr);
        } else {
            gin_C<64, true><<<GRID_MAIN, 256, smC64>>>(
                H, Wbf + OFF_W2L, b2_last, bnp, nullptr, mask, pe);
        }
    }
}

// round 8
// speedup vs baseline: 1.0348x; 1.0348x over previous
#include <cuda_runtime.h>
#include <cuda_bf16.h>
#include <cstdint>

#define NSUM 2048
#define NMAX 64
#define MFEAT 16
#define HID 128
#define OUTF 64
#define NEDGE 16384
#define NLAYER 4
#define NROWS_TOTAL (NSUM * NMAX)
#define GRID_MAIN 296

// bf16 weight buffer layout (n-major, stride = 2K+8, [hi K | lo K | pad])
#define SZ_W1F (128 * 40)
#define SZ_WR  (128 * 264)
#define SZ_W2L (64 * 264)
#define OFF_W1F 0
#define OFF_W1R (SZ_W1F)
#define OFF_W2M (OFF_W1R + 3 * SZ_WR)
#define OFF_W2L (OFF_W2M + 3 * SZ_WR)
#define WBF_TOTAL (OFF_W2L + SZ_W2L)

// ---------------------------------------------------------------------------
// Device scratch (static __device__ globals: allocation-free per harness rules)
// ---------------------------------------------------------------------------
__device__ float g_X[(size_t)NSUM * NMAX * HID];
__device__ float g_H[(size_t)NSUM * NMAX * HID];
__device__ __nv_bfloat16 g_Wbf[WBF_TOTAL];
__device__ float g_stats[NLAYER * 2 * HID];
__device__ int   g_off[NSUM + 1];
__device__ int   g_csr[NEDGE];

// ---------------------------------------------------------------------------
// Setup kernel (launch #1): CTA 0 builds CSR (count/scan/fill) + zeroes stats;
// CTAs 1..106 convert weights fp32 -> bf16 hi/lo n-major.
// ---------------------------------------------------------------------------
__global__ void __launch_bounds__(1024)
gin_setup(const int* __restrict__ src, const int* __restrict__ dst,
          const float* __restrict__ W1f, const float* __restrict__ W1r,
          const float* __restrict__ W2m, const float* __restrict__ W2l)
{
    const int t = threadIdx.x;            // 1024 threads
    if (blockIdx.x != 0) {
        // ---- weight conversion ----
        int idx = (blockIdx.x - 1) * 1024 + t;   // covers 106*1024 = 108544 exactly
        float w; int k, n, K; size_t doff; int sa;
        if (idx < 2048) {
            K = 16; k = idx / 128; n = idx % 128;
            w = W1f[idx]; doff = OFF_W1F; sa = 40;
        } else if (idx < 2048 + 3 * 16384) {
            int e = idx - 2048; int l = e / 16384; int r = e % 16384;
            K = 128; k = r / 128; n = r % 128;
            w = W1r[e]; doff = OFF_W1R + (size_t)l * SZ_WR; sa = 264;
        } else if (idx < 2048 + 6 * 16384) {
            int e = idx - 2048 - 3 * 16384; int l = e / 16384; int r = e % 16384;
            K = 128; k = r / 128; n = r % 128;
            w = W2m[e]; doff = OFF_W2M + (size_t)l * SZ_WR; sa = 264;
        } else {
            int e = idx - 2048 - 6 * 16384;
            K = 128; k = e / 64; n = e % 64;
            w = W2l[e]; doff = OFF_W2L; sa = 264;
        }
        __nv_bfloat16 hi = __float2bfloat16(w);
        __nv_bfloat16 lo = __float2bfloat16(w - __bfloat162float(hi));
        g_Wbf[doff + (size_t)n * sa + k]     = hi;
        g_Wbf[doff + (size_t)n * sa + K + k] = lo;
        return;
    }

    // ---- CSR build (single CTA) ----
    __shared__ int s0[NSUM], s1[NSUM], cur[NSUM];
    g_stats[t] = 0.f;                     // 4*2*128 == 1024 exactly
    #pragma unroll
    for (int j = 0; j < 2; j++) { s0[t + j * 1024] = 0; cur[t + j * 1024] = 0; }
    __syncthreads();

    #pragma unroll
    for (int j = 0; j < NEDGE / 1024; j++)
        atomicAdd(&s0[dst[t + j * 1024]], 1);
    __syncthreads();

    int* in = s0; int* out = s1;
    for (int d = 1; d < NSUM; d <<= 1) {
        #pragma unroll
        for (int j = 0; j < 2; j++) {
            int i = t + j * 1024;
            int v = in[i];
            if (i >= d) v += in[i - d];
            out[i] = v;
        }
        __syncthreads();
        int* tmp = in; in = out; out = tmp;
    }
    if (t == 0) g_off[0] = 0;
    #pragma unroll
    for (int j = 0; j < 2; j++) g_off[t + j * 1024 + 1] = in[t + j * 1024];
    __syncthreads();

    #pragma unroll
    for (int j = 0; j < NEDGE / 1024; j++) {
        int e = t + j * 1024;
        int d = dst[e];
        int p = atomicAdd(&cur[d], 1);
        int off = d ? in[d - 1] : 0;
        g_csr[off + p] = src[e];
    }
}

// ---------------------------------------------------------------------------
// MMA helpers
// ---------------------------------------------------------------------------
__device__ __forceinline__ void ldsm4(uint32_t* r, uint32_t a)
{
    asm volatile("ldmatrix.sync.aligned.m8n8.x4.shared.b16 {%0,%1,%2,%3}, [%4];"
                 : "=r"(r[0]), "=r"(r[1]), "=r"(r[2]), "=r"(r[3]) : "r"(a));
}

__device__ __forceinline__ void mma_bf16(float* d, const uint32_t* a, uint32_t b0, uint32_t b1)
{
    asm volatile("mma.sync.aligned.m16n8k16.row.col.f32.bf16.bf16.f32 "
                 "{%0,%1,%2,%3},{%4,%5,%6,%7},{%8,%9},{%0,%1,%2,%3};"
                 : "+f"(d[0]), "+f"(d[1]), "+f"(d[2]), "+f"(d[3])
                 : "r"(a[0]), "r"(a[1]), "r"(a[2]), "r"(a[3]), "r"(b0), "r"(b1));
}

// hi/lo bf16 convert + store of a float4 row-chunk
__device__ __forceinline__ void cvt_store(__nv_bfloat16* dhi, __nv_bfloat16* dlo, float4 v)
{
    __nv_bfloat16 h0 = __float2bfloat16(v.x), h1 = __float2bfloat16(v.y);
    __nv_bfloat16 h2 = __float2bfloat16(v.z), h3 = __float2bfloat16(v.w);
    __nv_bfloat162 a; a.x = h0; a.y = h1;
    __nv_bfloat162 b; b.x = h2; b.y = h3;
    ((__nv_bfloat162*)dhi)[0] = a; ((__nv_bfloat162*)dhi)[1] = b;
    __nv_bfloat162 c, d;
    c.x = __float2bfloat16(v.x - __bfloat162float(h0));
    c.y = __float2bfloat16(v.y - __bfloat162float(h1));
    d.x = __float2bfloat16(v.z - __bfloat162float(h2));
    d.y = __float2bfloat16(v.w - __bfloat162float(h3));
    ((__nv_bfloat162*)dlo)[0] = c; ((__nv_bfloat162*)dlo)[1] = d;
}

// GEMM core: 3 segments (hi*hi + lo*hi + hi*lo), KH/16 ksteps each.
template <int KH, int MT>
__device__ __forceinline__ void gemm_mma(const uint32_t* aBase, const uint32_t* bBase,
                                         int kaSel, int kbSel, float (*acc)[4][4])
{
    #pragma unroll
    for (int seg = 0; seg < 3; seg++) {
        const int aoff = (seg == 1) ? KH : 0;
        const int boff = (seg == 2) ? KH : 0;
        #pragma unroll
        for (int ks = 0; ks < KH / 16; ks++) {
            const int ka = (aoff + ks * 16 + kaSel) * 2;
            const int kb = (boff + ks * 16 + kbSel) * 2;
            uint32_t a[MT][4], b[2][4];
            #pragma unroll
            for (int mi = 0; mi < MT; mi++) ldsm4(a[mi], aBase[mi] + ka);
            #pragma unroll
            for (int p = 0; p < 2; p++) ldsm4(b[p], bBase[p] + kb);
            #pragma unroll
            for (int mi = 0; mi < MT; mi++)
                #pragma unroll
                for (int ni = 0; ni < 4; ni++)
                    mma_bf16(acc[mi][ni], a[mi], b[ni >> 1][(ni & 1) * 2], b[ni >> 1][(ni & 1) * 2 + 1]);
        }
    }
}

// ---------------------------------------------------------------------------
// Kernel A: gather + (1+eps)X + GEMM1 (bf16x3 MMA) + BN stat partials
// ---------------------------------------------------------------------------
template <int KH>
__global__ void __launch_bounds__(256, 2)
gin_A(const float* __restrict__ Xin, const __nv_bfloat16* __restrict__ Wg,
      const float* __restrict__ b1, const float* __restrict__ epsArr, int layer,
      float* __restrict__ Hout, float* __restrict__ gsum, float* __restrict__ gsq)
{
    constexpr int SA  = 2 * KH + 8;
    constexpr int KC4 = KH / 4;
    constexpr int EPT = 64 * KC4 / 256;
    extern __shared__ float smf[];
    __nv_bfloat16* Ws = (__nv_bfloat16*)smf;     // 128*SA
    __nv_bfloat16* As = Ws + 128 * SA;           // 64*SA
    float* sb = (float*)(As + 64 * SA);          // 128

    const int tid  = threadIdx.x;
    const int lane = tid & 31, wid = tid >> 5;
    const int wm = wid & 1, wn = wid >> 1;       // 2 (m) x 4 (n) warps
    const int grp = lane >> 2, tig = lane & 3;
    const int sel = lane >> 3, l7 = lane & 7;
    const float epl = 1.f + epsArr[layer];

    {   // stage weights + bias
        const uint4* s = (const uint4*)Wg;
        uint4* d = (uint4*)Ws;
        for (int i = tid; i < 128 * SA / 8; i += 256) d[i] = s[i];
        if (tid < 128) sb[tid] = b1[tid];
    }

    uint32_t aBase[2], bBase[2];
    {
        uint32_t asb = (uint32_t)__cvta_generic_to_shared(As);
        uint32_t wsb = (uint32_t)__cvta_generic_to_shared(Ws);
        aBase[0] = asb + (uint32_t)((wm * 32 + l7 + (sel & 1) * 8) * SA) * 2;
        aBase[1] = aBase[0] + 16 * SA * 2;
        bBase[0] = wsb + (uint32_t)((wn * 32 + l7 + (sel >> 1) * 8) * SA) * 2;
        bBase[1] = bBase[0] + 16 * SA * 2;
    }
    const int kaSel = (sel >> 1) * 8, kbSel = (sel & 1) * 8;

    float psum[8], psq[8];
    #pragma unroll
    for (int q = 0; q < 8; q++) { psum[q] = 0.f; psq[q] = 0.f; }

    __syncthreads();

    for (int n = blockIdx.x; n < NSUM; n += GRID_MAIN) {
        // ---- gather: Z = (1+eps)X[n] + sum X[src] ----
        float4 r[EPT];
        const float4* xn = (const float4*)(Xin + (size_t)n * 64 * KH);
        #pragma unroll
        for (int j = 0; j < EPT; j++) {
            float4 v = xn[tid + j * 256];
            r[j].x = v.x * epl; r[j].y = v.y * epl; r[j].z = v.z * epl; r[j].w = v.w * epl;
        }
        const int eE = g_off[n + 1];
        for (int e = g_off[n]; e < eE; e++) {
            const float4* xs = (const float4*)(Xin + (size_t)g_csr[e] * 64 * KH);
            #pragma unroll
            for (int j = 0; j < EPT; j++) {
                float4 v = xs[tid + j * 256];
                r[j].x += v.x; r[j].y += v.y; r[j].z += v.z; r[j].w += v.w;
            }
        }
        #pragma unroll
        for (int j = 0; j < EPT; j++) {
            int i = tid + j * 256;
            int row = i / KC4, col = (i % KC4) * 4;
            cvt_store(&As[row * SA + col], &As[row * SA + KH + col], r[j]);
        }
        __syncthreads();

        // ---- GEMM ----
        float acc[2][4][4];
        #pragma unroll
        for (int mi = 0; mi < 2; mi++)
            #pragma unroll
            for (int ni = 0; ni < 4; ni++) {
                int c0 = wn * 32 + ni * 8 + tig * 2;
                acc[mi][ni][0] = sb[c0];     acc[mi][ni][1] = sb[c0 + 1];
                acc[mi][ni][2] = sb[c0];     acc[mi][ni][3] = sb[c0 + 1];
            }
        gemm_mma<KH, 2>(aBase, bBase, kaSel, kbSel, acc);

        // ---- epilogue: H + BN partials ----
        float* hb = Hout + (size_t)n * 64 * 128;
        #pragma unroll
        for (int mi = 0; mi < 2; mi++) {
            int r0 = wm * 32 + mi * 16 + grp;
            #pragma unroll
            for (int ni = 0; ni < 4; ni++) {
                int c0 = wn * 32 + ni * 8 + tig * 2;
                float2 v0 = make_float2(acc[mi][ni][0], acc[mi][ni][1]);
                float2 v1 = make_float2(acc[mi][ni][2], acc[mi][ni][3]);
                *(float2*)&hb[(size_t)r0 * 128 + c0]       = v0;
                *(float2*)&hb[(size_t)(r0 + 8) * 128 + c0] = v1;
                psum[ni * 2 + 0] += v0.x + v1.x;
                psum[ni * 2 + 1] += v0.y + v1.y;
                psq[ni * 2 + 0]  += v0.x * v0.x + v1.x * v1.x;
                psq[ni * 2 + 1]  += v0.y * v0.y + v1.y * v1.y;
            }
        }
        __syncthreads();
    }

    // ---- CTA-end BN reduction (shuffle, then global atomics) ----
    #pragma unroll
    for (int q = 0; q < 8; q++) {
        float s = psum[q], ss = psq[q];
        s  += __shfl_xor_sync(0xffffffffu, s, 4);
        s  += __shfl_xor_sync(0xffffffffu, s, 8);
        s  += __shfl_xor_sync(0xffffffffu, s, 16);
        ss += __shfl_xor_sync(0xffffffffu, ss, 4);
        ss += __shfl_xor_sync(0xffffffffu, ss, 8);
        ss += __shfl_xor_sync(0xffffffffu, ss, 16);
        if (lane < 4) {
            int c = wn * 32 + (q >> 1) * 8 + lane * 2 + (q & 1);
            atomicAdd(&gsum[c], s);
            atomicAdd(&gsq[c], ss);
        }
    }
}

// ---------------------------------------------------------------------------
// Kernel C: BN(params computed in-CTA) + ReLU + GEMM2; LAST fuses masked PE
// ---------------------------------------------------------------------------
template <int NOUT, bool LAST>
__global__ void __launch_bounds__(256, 2)
gin_C(const float* __restrict__ Hin, const __nv_bfloat16* __restrict__ Wg,
      const float* __restrict__ b2,
      const float* __restrict__ gsum, const float* __restrict__ gsq,
      const float* __restrict__ gamma, const float* __restrict__ beta,
      float* __restrict__ Xout, const float* __restrict__ mask, float* __restrict__ pe)
{
    constexpr int KH = 128, SA = 264;
    constexpr int WGM = (NOUT == 128) ? 2 : 4;
    constexpr int MT  = (NOUT == 128) ? 2 : 1;
    extern __shared__ float smf[];
    __nv_bfloat16* Ws = (__nv_bfloat16*)smf;     // NOUT*SA
    __nv_bfloat16* As = Ws + NOUT * SA;          // 64*SA
    float* sb  = (float*)(As + 64 * SA);         // NOUT
    float* ssc = sb + NOUT;                      // 128
    float* ssh = ssc + 128;                      // 128
    float* spe = ssh + 128;                      // 64 (LAST only)

    const int tid  = threadIdx.x;
    const int lane = tid & 31, wid = tid >> 5;
    const int wm = wid % WGM, wn = wid / WGM;
    const int grp = lane >> 2, tig = lane & 3;
    const int sel = lane >> 3, l7 = lane & 7;
    const int rowbase = wm * MT * 16, colbase = wn * 32;

    {
        const uint4* s = (const uint4*)Wg;
        uint4* d = (uint4*)Ws;
        for (int i = tid; i < NOUT * SA / 8; i += 256) d[i] = s[i];
        if (tid < NOUT) sb[tid] = b2[tid];
        if (tid < 128) {
            // BN finalize in-CTA (replaces the old gin_bn kernel)
            const float inv = 1.f / (float)NROWS_TOTAL;
            float mu  = gsum[tid] * inv;
            float var = gsq[tid] * inv - mu * mu;
            float rs  = rsqrtf(var + 1e-5f);
            float scl = rs * gamma[tid];
            ssc[tid] = scl;
            ssh[tid] = beta[tid] - mu * scl;
        }
    }

    uint32_t aBase[MT], bBase[2];
    {
        uint32_t asb = (uint32_t)__cvta_generic_to_shared(As);
        uint32_t wsb = (uint32_t)__cvta_generic_to_shared(Ws);
        #pragma unroll
        for (int mi = 0; mi < MT; mi++)
            aBase[mi] = asb + (uint32_t)((rowbase + mi * 16 + l7 + (sel & 1) * 8) * SA) * 2;
        bBase[0] = wsb + (uint32_t)((colbase + l7 + (sel >> 1) * 8) * SA) * 2;
        bBase[1] = bBase[0] + 16 * SA * 2;
    }
    const int kaSel = (sel >> 1) * 8, kbSel = (sel & 1) * 8;

    __syncthreads();

    for (int n = blockIdx.x; n < NSUM; n += GRID_MAIN) {
        // ---- BN + ReLU + hi/lo convert into A ----
        const float4* h4 = (const float4*)(Hin + (size_t)n * 64 * 128);
        #pragma unroll
        for (int j = 0; j < 8; j++) {
            int i = tid + j * 256;
            int row = i >> 5, col = (i & 31) * 4;
            float4 h = h4[i];
            float4 sc = *(const float4*)&ssc[col];
            float4 sh = *(const float4*)&ssh[col];
            float4 a;
            a.x = fmaxf(fmaf(h.x, sc.x, sh.x), 0.f);
            a.y = fmaxf(fmaf(h.y, sc.y, sh.y), 0.f);
            a.z = fmaxf(fmaf(h.z, sc.z, sh.z), 0.f);
            a.w = fmaxf(fmaf(h.w, sc.w, sh.w), 0.f);
            cvt_store(&As[row * SA + col], &As[row * SA + KH + col], a);
        }
        __syncthreads();

        // ---- GEMM ----
        float acc[MT][4][4];
        #pragma unroll
        for (int mi = 0; mi < MT; mi++)
            #pragma unroll
            for (int ni = 0; ni < 4; ni++) {
                int c0 = colbase + ni * 8 + tig * 2;
                acc[mi][ni][0] = sb[c0];     acc[mi][ni][1] = sb[c0 + 1];
                acc[mi][ni][2] = sb[c0];     acc[mi][ni][3] = sb[c0 + 1];
            }
        gemm_mma<KH, MT>(aBase, bBase, kaSel, kbSel, acc);

        if (!LAST) {
            float* xb = Xout + (size_t)n * 64 * 128;
            #pragma unroll
            for (int mi = 0; mi < MT; mi++) {
                int r0 = rowbase + mi * 16 + grp;
                #pragma unroll
                for (int ni = 0; ni < 4; ni++) {
                    int c0 = colbase + ni * 8 + tig * 2;
                    *(float2*)&xb[(size_t)r0 * 128 + c0]       = make_float2(acc[mi][ni][0], acc[mi][ni][1]);
                    *(float2*)&xb[(size_t)(r0 + 8) * 128 + c0] = make_float2(acc[mi][ni][2], acc[mi][ni][3]);
                }
            }
        } else {
            if (tid < 64) spe[tid] = 0.f;
            __syncthreads();
            float m0 = mask[(size_t)n * 64 + rowbase + grp];
            float m1 = mask[(size_t)n * 64 + rowbase + grp + 8];
            #pragma unroll
            for (int ni = 0; ni < 4; ni++) {
                float p0 = m0 * acc[0][ni][0] + m1 * acc[0][ni][2];
                float p1 = m0 * acc[0][ni][1] + m1 * acc[0][ni][3];
                p0 += __shfl_xor_sync(0xffffffffu, p0, 4);
                p0 += __shfl_xor_sync(0xffffffffu, p0, 8);
                p0 += __shfl_xor_sync(0xffffffffu, p0, 16);
                p1 += __shfl_xor_sync(0xffffffffu, p1, 4);
                p1 += __shfl_xor_sync(0xffffffffu, p1, 8);
                p1 += __shfl_xor_sync(0xffffffffu, p1, 16);
                if (lane < 4) {
                    int c = colbase + ni * 8 + lane * 2;
                    atomicAdd(&spe[c], p0);
                    atomicAdd(&spe[c + 1], p1);
                }
            }
            __syncthreads();
            if (tid < 64) pe[(size_t)n * 64 + tid] = spe[tid];
        }
        __syncthreads();
    }
}

// ---------------------------------------------------------------------------
// Host-side launch
// ---------------------------------------------------------------------------
extern "C" void kernel_launch(void* const* d_in, const int* in_sizes, int n_in,
                              void* d_out, int out_size)
{
    const float* W        = (const float*)d_in[0];
    const float* mask     = (const float*)d_in[1];
    const int*   src      = (const int*)d_in[2];
    const int*   dst      = (const int*)d_in[3];
    const float* eps      = (const float*)d_in[4];
    const float* W1_first = (const float*)d_in[5];
    const float* b1_first = (const float*)d_in[6];
    const float* W1_rest  = (const float*)d_in[7];
    const float* b1_rest  = (const float*)d_in[8];
    const float* bn_gamma = (const float*)d_in[9];
    const float* bn_beta  = (const float*)d_in[10];
    const float* W2_mid   = (const float*)d_in[11];
    const float* b2_mid   = (const float*)d_in[12];
    const float* W2_last  = (const float*)d_in[13];
    const float* b2_last  = (const float*)d_in[14];
    float* pe = (float*)d_out;

    void *pX, *pH, *pW, *pStats;
    cudaGetSymbolAddress(&pX, g_X);
    cudaGetSymbolAddress(&pH, g_H);
    cudaGetSymbolAddress(&pW, g_Wbf);
    cudaGetSymbolAddress(&pStats, g_stats);
    float* X  = (float*)pX;
    float* H  = (float*)pH;
    __nv_bfloat16* Wbf = (__nv_bfloat16*)pW;
    float* st = (float*)pStats;

    const int smA128 = (192 * 264) * 2 + 512;                  // 101888
    const int smA16  = (192 * 40) * 2 + 512;                   // 15872
    const int smC128 = (192 * 264) * 2 + 512 + 1024;           // 102912
    const int smC64  = (128 * 264) * 2 + 256 + 1024 + 256;     // 69120

    cudaFuncSetAttribute(gin_A<128>,        cudaFuncAttributeMaxDynamicSharedMemorySize, smA128);
    cudaFuncSetAttribute(gin_A<16>,         cudaFuncAttributeMaxDynamicSharedMemorySize, smA16);
    cudaFuncSetAttribute(gin_C<128, false>, cudaFuncAttributeMaxDynamicSharedMemorySize, smC128);
    cudaFuncSetAttribute(gin_C<64, true>,   cudaFuncAttributeMaxDynamicSharedMemorySize, smC64);

    // Launch order: setup(1), A16(2), C128(3), A128(4) <- ncu captures #4
    gin_setup<<<107, 1024>>>(src, dst, W1_first, W1_rest, W2_mid, W2_last);

    for (int l = 0; l < NLAYER; l++) {
        float* gsum = st + l * 2 * HID;
        float* gsq  = gsum + HID;

        if (l == 0) {
            gin_A<16><<<GRID_MAIN, 256, smA16>>>(
                W, Wbf + OFF_W1F, b1_first, eps, 0, H, gsum, gsq);
        } else {
            gin_A<128><<<GRID_MAIN, 256, smA128>>>(
                X, Wbf + OFF_W1R + (size_t)(l - 1) * SZ_WR,
                b1_rest + (size_t)(l - 1) * HID, eps, l, H, gsum, gsq);
        }

        if (l < NLAYER - 1) {
            gin_C<128, false><<<GRID_MAIN, 256, smC128>>>(
                H, Wbf + OFF_W2M + (size_t)l * SZ_WR, b2_mid + (size_t)l * HID,
                gsum, gsq, bn_gamma + (size_t)l * HID, bn_beta + (size_t)l * HID,
                X, nullptr, nullptr);
        } else {
            gin_C<64, true><<<GRID_MAIN, 256, smC64>>>(
                H, Wbf + OFF_W2L, b2_last,
                gsum, gsq, bn_gamma + (size_t)l * HID, bn_beta + (size_t)l * HID,
                nullptr, mask, pe);
        }
    }
}